// round 1
// baseline (speedup 1.0000x reference)
#include <cuda_runtime.h>
#include <cuda_bf16.h>

// CRF forward (logsumexp scan) in the exp domain.
//   E = exp(transitions) precomputed (bf16, 8MB, sliced into SMEM per CTA)
//   per step: GEMV s = E*W, renormalize by r=max(W), track log offset L.
// Persistent kernel, 128 co-resident CTAs, custom grid barrier per step.

#define T 2048
#define ROWS 16
#define NBLK (T / ROWS)   // 128
#define NTHR 256
#define START_IDX 0
#define END_IDX 1

// ---- device scratch (no allocations allowed) ----
__device__ __align__(16) __nv_bfloat16 g_E[(size_t)T * T];   // 8 MB
__device__ __align__(16) __nv_bfloat16 g_W[2][T];
__device__ unsigned g_arrive;
__device__ volatile unsigned g_release;

// dynamic smem layout
#define SMEM_E_BYTES   (ROWS * T * 2)          // 65536
#define SMEM_W_OFF     SMEM_E_BYTES
#define SMEM_W_BYTES   (T / 8 * 16)            // 4096 (256 x uint4 of bf16)
#define SMEM_EMIT_OFF  (SMEM_W_OFF + SMEM_W_BYTES)
#define SMEM_RED_OFF   (SMEM_EMIT_OFF + ROWS * 4)
#define SMEM_TOTAL     (SMEM_RED_OFF + 8 * 4)

__device__ __forceinline__ float bflo(unsigned p) { return __uint_as_float(p << 16); }
__device__ __forceinline__ float bfhi(unsigned p) { return __uint_as_float(p & 0xffff0000u); }

__global__ void crf_init(const float* __restrict__ trans) {
    size_t idx = (size_t)blockIdx.x * blockDim.x + threadIdx.x;
    size_t stride = (size_t)gridDim.x * blockDim.x;
    for (size_t i = idx; i < (size_t)T * T; i += stride)
        g_E[i] = __float2bfloat16(__expf(trans[i]));
    if (idx < T) {
        g_W[0][idx] = __float2bfloat16(idx == START_IDX ? 1.0f : 0.0f);
        g_W[1][idx] = __float2bfloat16(0.0f);
    }
    if (idx == 0) { g_arrive = 0; g_release = 0; }
}

#define ACCUM8(ea, accA, accB)                                           \
    do {                                                                 \
        accA = fmaf(bflo((ea).x), w0, accA);                             \
        accB = fmaf(bfhi((ea).x), w1, accB);                             \
        accA = fmaf(bflo((ea).y), w2, accA);                             \
        accB = fmaf(bfhi((ea).y), w3, accB);                             \
        accA = fmaf(bflo((ea).z), w4, accA);                             \
        accB = fmaf(bfhi((ea).z), w5, accB);                             \
        accA = fmaf(bflo((ea).w), w6, accA);                             \
        accB = fmaf(bfhi((ea).w), w7, accB);                             \
    } while (0)

__global__ void __launch_bounds__(NTHR, 1)
crf_main(const float* __restrict__ h, const float* __restrict__ trans,
         float* __restrict__ out, int S) {
    extern __shared__ unsigned char smem_raw[];
    __nv_bfloat16* sE = (__nv_bfloat16*)smem_raw;
    uint4* swv = (uint4*)(smem_raw + SMEM_W_OFF);     // W as 256 x uint4 (bf16x8)
    float* emitv = (float*)(smem_raw + SMEM_EMIT_OFF);
    float* red = (float*)(smem_raw + SMEM_RED_OFF);

    const int tid = threadIdx.x;
    const int wid = tid >> 5;
    const int ln = tid & 31;
    const int r0 = blockIdx.x * ROWS;

    // Load this CTA's 16 E-rows into SMEM (once).
    {
        const uint4* gE4 = (const uint4*)(g_E + (size_t)r0 * T);
        uint4* sE4w = (uint4*)sE;
        for (int i = tid; i < ROWS * T / 8; i += NTHR) sE4w[i] = gE4[i];
    }
    __syncthreads();

    const uint4* sE4 = (const uint4*)sE;
    const uint4* e0p = sE4 + (2 * wid) * (T / 8);
    const uint4* e1p = sE4 + (2 * wid + 1) * (T / 8);

    float L = 0.0f;
    int cur = 0;

    for (int t = 0; t < S; t++) {
        // prefetch this step's emissions for my rows
        if (tid < ROWS) emitv[tid] = h[(size_t)t * T + r0 + tid];

        // load W (bypass L1 — written by other SMs last step), compute max
        const uint4* gW4 = (const uint4*)(g_W[cur]);
        uint4 v = __ldcv(gW4 + tid);
        swv[tid] = v;
        float m = fmaxf(fmaxf(fmaxf(bflo(v.x), bfhi(v.x)), fmaxf(bflo(v.y), bfhi(v.y))),
                        fmaxf(fmaxf(bflo(v.z), bfhi(v.z)), fmaxf(bflo(v.w), bfhi(v.w))));
        #pragma unroll
        for (int off = 16; off; off >>= 1)
            m = fmaxf(m, __shfl_xor_sync(0xffffffffu, m, off));
        if (ln == 0) red[wid] = m;
        __syncthreads();

        float r = red[0];
        #pragma unroll
        for (int q = 1; q < 8; q++) r = fmaxf(r, red[q]);
        float rinv = 1.0f / r;
        L += __logf(r);   // identical in every block (same data, same order)

        // dot products: warp wid owns global rows r0+2*wid, r0+2*wid+1
        float a00 = 0.f, a01 = 0.f, a10 = 0.f, a11 = 0.f;
        #pragma unroll
        for (int k = 0; k < 8; k++) {
            int jv = (k << 5) + ln;
            uint4 wv = swv[jv];
            float w0 = bflo(wv.x), w1 = bfhi(wv.x);
            float w2 = bflo(wv.y), w3 = bfhi(wv.y);
            float w4 = bflo(wv.z), w5 = bfhi(wv.z);
            float w6 = bflo(wv.w), w7 = bfhi(wv.w);
            uint4 ea = e0p[jv];
            ACCUM8(ea, a00, a01);
            uint4 eb = e1p[jv];
            ACCUM8(eb, a10, a11);
        }
        float s0 = a00 + a01;
        float s1 = a10 + a11;
        #pragma unroll
        for (int off = 16; off; off >>= 1) {
            s0 += __shfl_xor_sync(0xffffffffu, s0, off);
            s1 += __shfl_xor_sync(0xffffffffu, s1, off);
        }
        if (ln == 0) {
            int nxt = cur ^ 1;
            float n0 = s0 * rinv * __expf(emitv[2 * wid]);
            float n1 = s1 * rinv * __expf(emitv[2 * wid + 1]);
            g_W[nxt][r0 + 2 * wid]     = __float2bfloat16(n0);
            g_W[nxt][r0 + 2 * wid + 1] = __float2bfloat16(n1);
        }

        // ---- grid barrier (counter + monotonic release generation) ----
        __syncthreads();
        if (tid == 0) {
            __threadfence();
            unsigned a = atomicAdd(&g_arrive, 1);
            if (a == NBLK - 1) {
                atomicExch(&g_arrive, 0);
                __threadfence();
                atomicAdd((unsigned*)&g_release, 1);
            } else {
                while (g_release < (unsigned)(t + 1)) { }
            }
        }
        __syncthreads();
        cur ^= 1;
    }

    // terminal: logZ = log( sum_j W_S[j] * exp(tr[END, j]) ) + L
    if (blockIdx.x == 0) {
        const uint4* gW4 = (const uint4*)(g_W[cur]);
        uint4 v = __ldcv(gW4 + tid);
        const float* te = trans + (size_t)END_IDX * T;
        int j0 = tid * 8;
        float p = 0.f;
        p += bflo(v.x) * __expf(te[j0 + 0]);
        p += bfhi(v.x) * __expf(te[j0 + 1]);
        p += bflo(v.y) * __expf(te[j0 + 2]);
        p += bfhi(v.y) * __expf(te[j0 + 3]);
        p += bflo(v.z) * __expf(te[j0 + 4]);
        p += bfhi(v.z) * __expf(te[j0 + 5]);
        p += bflo(v.w) * __expf(te[j0 + 6]);
        p += bfhi(v.w) * __expf(te[j0 + 7]);
        #pragma unroll
        for (int off = 16; off; off >>= 1)
            p += __shfl_xor_sync(0xffffffffu, p, off);
        if (ln == 0) red[wid] = p;
        __syncthreads();
        if (tid == 0) {
            float tot = 0.f;
            for (int q = 0; q < 8; q++) tot += red[q];
            out[0] = __logf(tot) + L;
        }
    }
}

extern "C" void kernel_launch(void* const* d_in, const int* in_sizes, int n_in,
                              void* d_out, int out_size) {
    const float* h = (const float*)d_in[0];
    const float* trans = (const float*)d_in[1];
    float* out = (float*)d_out;
    int S = in_sizes[0] / T;

    cudaFuncSetAttribute(crf_main, cudaFuncAttributeMaxDynamicSharedMemorySize,
                         SMEM_TOTAL);

    crf_init<<<512, 256>>>(trans);
    crf_main<<<NBLK, NTHR, SMEM_TOTAL>>>(h, trans, out, S);
}